// round 1
// baseline (speedup 1.0000x reference)
#include <cuda_runtime.h>

typedef unsigned long long u64;

#define EE 10
#define TT 50
#define NB 65536
#define RPT 2
#define NTHREADS (NB / RPT)   // 32768

// Fused weight buffer layout (floats):
// [0..319]   XW: per-k rows of 32: {A_r[k][0..9], A_z[k][0..9], A_h[k][0..9], pad2}
// [320..519] HW: per-k rows of 20: {B_r[k][0..9], B_z[k][0..9]}
// [520..639] GW: per-k rows of 12: {B_h[k][0..9], pad2}
// [640..671] C:  {c_r[0..9], c_z[0..9], c_h[0..9], pad2}
__device__ float g_fw[672];

__global__ void fuse_kernel(
    const float* __restrict__ Wi_r, const float* __restrict__ bi_r,
    const float* __restrict__ Wh_r, const float* __restrict__ Ws_r, const float* __restrict__ bs_r,
    const float* __restrict__ Wi_z, const float* __restrict__ bi_z,
    const float* __restrict__ Wh_z, const float* __restrict__ Ws_z, const float* __restrict__ bs_z,
    const float* __restrict__ Wi_h, const float* __restrict__ bi_h,
    const float* __restrict__ Wh_h, const float* __restrict__ Wt_h, const float* __restrict__ bt_h)
{
    int tid = threadIdx.x;
    for (int i = tid; i < 672; i += blockDim.x) g_fw[i] = 0.0f;
    __syncthreads();
    for (int idx = tid; idx < 630; idx += blockDim.x) {
        if (idx < 300) {
            int mat = idx / 100, rem = idx % 100, k = rem / 10, j = rem % 10;
            const float* Wi = (mat == 0) ? Wi_r : ((mat == 1) ? Wi_z : Wi_h);
            const float* Ws = (mat == 0) ? Ws_r : ((mat == 1) ? Ws_z : Wt_h);
            float s = 0.0f;
            for (int m = 0; m < 10; ++m) s += Wi[k*10+m] * Ws[m*10+j];
            g_fw[k*32 + mat*10 + j] = s;
        } else if (idx < 500) {
            int m2 = idx - 300; int mat = m2 / 100, rem = m2 % 100, k = rem/10, j = rem%10;
            const float* Wh = (mat == 0) ? Wh_r : Wh_z;
            const float* Ws = (mat == 0) ? Ws_r : Ws_z;
            float s = 0.0f;
            for (int m = 0; m < 10; ++m) s += Wh[k*10+m] * Ws[m*10+j];
            g_fw[320 + k*20 + mat*10 + j] = s;
        } else if (idx < 600) {
            int m2 = idx - 500; int k = m2/10, j = m2%10;
            float s = 0.0f;
            for (int m = 0; m < 10; ++m) s += Wh_h[k*10+m] * Wt_h[m*10+j];
            g_fw[520 + k*12 + j] = s;
        } else {
            int m2 = idx - 600; int mat = m2/10, j = m2%10;
            const float* bi = (mat==0) ? bi_r : ((mat==1) ? bi_z : bi_h);
            const float* Ws = (mat==0) ? Ws_r : ((mat==1) ? Ws_z : Wt_h);
            const float* bs = (mat==0) ? bs_r : ((mat==1) ? bs_z : bt_h);
            float s = bs[j];
            for (int m = 0; m < 10; ++m) s += bi[m]*Ws[m*10+j];
            g_fw[640 + mat*10 + j] = s;
        }
    }
}

__device__ __forceinline__ u64 pk2(float v) {
    u64 r; asm("mov.b64 %0, {%1, %1};" : "=l"(r) : "f"(v)); return r;
}
__device__ __forceinline__ void ff2(u64 &d, u64 a, u64 b) {
    asm("fma.rn.f32x2 %0, %1, %2, %0;" : "+l"(d) : "l"(a), "l"(b));
}
__device__ __forceinline__ void up2(u64 v, float &lo, float &hi) {
    asm("mov.b64 {%0, %1}, %2;" : "=f"(lo), "=f"(hi) : "l"(v));
}
__device__ __forceinline__ float fast_sigmoid(float x) {
    float e; asm("ex2.approx.f32 %0, %1;" : "=f"(e) : "f"(-1.4426950408889634f * x));
    float r; asm("rcp.approx.f32 %0, %1;" : "=f"(r) : "f"(1.0f + e));
    return r;
}
__device__ __forceinline__ float fast_tanh(float x) {
    // tanh(x) = 2*sigmoid(2x) - 1
    float e; asm("ex2.approx.f32 %0, %1;" : "=f"(e) : "f"(-2.8853900817779268f * x));
    float r; asm("rcp.approx.f32 %0, %1;" : "=f"(r) : "f"(1.0f + e));
    return 2.0f * r - 1.0f;
}

__global__ void __launch_bounds__(32) augru_kernel(
    const float* __restrict__ X, const float* __restrict__ Aat,
    const float* __restrict__ h0, float* __restrict__ out)
{
    __shared__ __align__(16) float sw[672];
    int tid = threadIdx.x;
    for (int i = tid; i < 672; i += 32) sw[i] = g_fw[i];
    __syncthreads();

    int g = blockIdx.x * 32 + tid;   // 0..NTHREADS-1
    int row0 = g;
    int row1 = g + NTHREADS;

    float h[RPT][EE];
    #pragma unroll
    for (int j = 0; j < EE; ++j) { float v = __ldg(h0 + j); h[0][j] = v; h[1][j] = v; }

    const float* xp[RPT]; const float* ap[RPT];
    xp[0] = X + (size_t)row0 * (TT*EE);  xp[1] = X + (size_t)row1 * (TT*EE);
    ap[0] = Aat + (size_t)row0 * (TT*EE); ap[1] = Aat + (size_t)row1 * (TT*EE);

    float x[RPT][EE], xn[RPT][EE], a[RPT][EE];
    #pragma unroll
    for (int r2 = 0; r2 < RPT; ++r2) {
        #pragma unroll
        for (int j = 0; j < 5; ++j) {
            float2 v = *(const float2*)(xp[r2] + 2*j);
            x[r2][2*j] = v.x; x[r2][2*j+1] = v.y;
        }
    }

    for (int t = 0; t < TT; ++t) {
        // a_t: issued now, consumed at end of the step (latency self-hidden)
        #pragma unroll
        for (int r2 = 0; r2 < RPT; ++r2) {
            #pragma unroll
            for (int j = 0; j < 5; ++j) {
                float2 v = *(const float2*)(ap[r2] + t*EE + 2*j);
                a[r2][2*j] = v.x; a[r2][2*j+1] = v.y;
            }
        }
        // prefetch x_{t+1}
        if (t + 1 < TT) {
            #pragma unroll
            for (int r2 = 0; r2 < RPT; ++r2) {
                #pragma unroll
                for (int j = 0; j < 5; ++j) {
                    float2 v = *(const float2*)(xp[r2] + (t+1)*EE + 2*j);
                    xn[r2][2*j] = v.x; xn[r2][2*j+1] = v.y;
                }
            }
        }

        // init accumulators from fused biases
        u64 aR[RPT][5], aZ[RPT][5], aH[RPT][5];
        {
            const ulonglong2* c2 = (const ulonglong2*)(sw + 640);
            u64 cc[16];
            #pragma unroll
            for (int i = 0; i < 8; ++i) { ulonglong2 v = c2[i]; cc[2*i] = v.x; cc[2*i+1] = v.y; }
            #pragma unroll
            for (int j = 0; j < 5; ++j) {
                aR[0][j] = cc[j];    aR[1][j] = cc[j];
                aZ[0][j] = cc[5+j];  aZ[1][j] = cc[5+j];
                aH[0][j] = cc[10+j]; aH[1][j] = cc[10+j];
            }
        }

        // phase 1: x and h contributions (all gates)
        #pragma unroll
        for (int k = 0; k < EE; ++k) {
            const ulonglong2* xw2 = (const ulonglong2*)(sw + k*32);
            const ulonglong2* hw2 = (const ulonglong2*)(sw + 320 + k*20);
            u64 wx[16], wh[10];
            #pragma unroll
            for (int i = 0; i < 8; ++i) { ulonglong2 v = xw2[i]; wx[2*i] = v.x; wx[2*i+1] = v.y; }
            #pragma unroll
            for (int i = 0; i < 5; ++i) { ulonglong2 v = hw2[i]; wh[2*i] = v.x; wh[2*i+1] = v.y; }

            u64 px0 = pk2(x[0][k]), px1 = pk2(x[1][k]);
            u64 ph0 = pk2(h[0][k]), ph1 = pk2(h[1][k]);
            #pragma unroll
            for (int j = 0; j < 5; ++j) {
                ff2(aR[0][j], px0, wx[j]);    ff2(aR[1][j], px1, wx[j]);
                ff2(aZ[0][j], px0, wx[5+j]);  ff2(aZ[1][j], px1, wx[5+j]);
                ff2(aH[0][j], px0, wx[10+j]); ff2(aH[1][j], px1, wx[10+j]);
                ff2(aR[0][j], ph0, wh[j]);    ff2(aR[1][j], ph1, wh[j]);
                ff2(aZ[0][j], ph0, wh[5+j]);  ff2(aZ[1][j], ph1, wh[5+j]);
            }
        }

        // phase 2: gates
        float rg[RPT][EE], zg[RPT][EE];
        #pragma unroll
        for (int r2 = 0; r2 < RPT; ++r2) {
            #pragma unroll
            for (int j = 0; j < 5; ++j) {
                float lo, hi;
                up2(aR[r2][j], lo, hi);
                rg[r2][2*j] = fast_sigmoid(lo); rg[r2][2*j+1] = fast_sigmoid(hi);
                up2(aZ[r2][j], lo, hi);
                zg[r2][2*j] = fast_sigmoid(lo); zg[r2][2*j+1] = fast_sigmoid(hi);
            }
        }

        // phase 2b: (h*z) @ B_h
        #pragma unroll
        for (int k = 0; k < EE; ++k) {
            const u64* gw = (const u64*)(sw + 520 + k*12);
            const ulonglong2* gw2 = (const ulonglong2*)gw;
            u64 wg[5];
            { ulonglong2 v0 = gw2[0], v1 = gw2[1];
              wg[0] = v0.x; wg[1] = v0.y; wg[2] = v1.x; wg[3] = v1.y; wg[4] = gw[4]; }
            u64 pg0 = pk2(h[0][k] * zg[0][k]);
            u64 pg1 = pk2(h[1][k] * zg[1][k]);
            #pragma unroll
            for (int j = 0; j < 5; ++j) { ff2(aH[0][j], pg0, wg[j]); ff2(aH[1][j], pg1, wg[j]); }
        }

        // phase 3: candidate + update
        #pragma unroll
        for (int r2 = 0; r2 < RPT; ++r2) {
            #pragma unroll
            for (int j = 0; j < 5; ++j) {
                float lo, hi; up2(aH[r2][j], lo, hi);
                float hc0 = fast_tanh(lo), hc1 = fast_tanh(hi);
                int j0 = 2*j, j1 = 2*j + 1;
                float Ra0 = a[r2][j0] * rg[r2][j0];
                float Ra1 = a[r2][j1] * rg[r2][j1];
                h[r2][j0] += Ra0 * (hc0 - h[r2][j0]);
                h[r2][j1] += Ra1 * (hc1 - h[r2][j1]);
            }
        }

        // rotate prefetch buffers
        #pragma unroll
        for (int r2 = 0; r2 < RPT; ++r2) {
            #pragma unroll
            for (int j = 0; j < EE; ++j) x[r2][j] = xn[r2][j];
        }
    }

    // write h_final
    #pragma unroll
    for (int j = 0; j < 5; ++j) {
        *(float2*)(out + (size_t)row0*EE + 2*j) = make_float2(h[0][2*j], h[0][2*j+1]);
    }
    #pragma unroll
    for (int j = 0; j < 5; ++j) {
        *(float2*)(out + (size_t)row1*EE + 2*j) = make_float2(h[1][2*j], h[1][2*j+1]);
    }
}

extern "C" void kernel_launch(void* const* d_in, const int* in_sizes, int n_in,
                              void* d_out, int out_size)
{
    const float* Xg = (const float*)d_in[0];
    const float* Ag = (const float*)d_in[1];
    const float* h0 = (const float*)d_in[2];

    fuse_kernel<<<1, 256>>>(
        (const float*)d_in[3],  (const float*)d_in[4],  (const float*)d_in[5],
        (const float*)d_in[6],  (const float*)d_in[7],
        (const float*)d_in[8],  (const float*)d_in[9],  (const float*)d_in[10],
        (const float*)d_in[11], (const float*)d_in[12],
        (const float*)d_in[13], (const float*)d_in[14], (const float*)d_in[15],
        (const float*)d_in[16], (const float*)d_in[17]);

    augru_kernel<<<NTHREADS / 32, 32>>>(Xg, Ag, h0, (float*)d_out);
}

// round 2
// speedup vs baseline: 1.2170x; 1.2170x over previous
#include <cuda_runtime.h>

typedef unsigned long long u64;

#define EE 10
#define TT 50
#define NB 65536
#define BTH 64          // threads per block = rows per block
#define CH 5            // timesteps per staged chunk
#define NCHUNK (TT/CH)  // 10
#define ROWSTRIDE 51    // smem row stride (floats), gcd(51,32)=1 -> conflict-free

// Fused weight buffer layout (floats):
// [0..319]   XW: per-k rows of 32: {A_r[k][0..9], A_z[k][0..9], A_h[k][0..9], pad2}
// [320..519] HW: per-k rows of 20: {B_r[k][0..9], B_z[k][0..9]}
// [520..639] GW: per-k rows of 12: {B_h[k][0..9], pad2}
// [640..671] C:  {c_r[0..9], c_z[0..9], c_h[0..9], pad2}
__device__ float g_fw[672];

__global__ void fuse_kernel(
    const float* __restrict__ Wi_r, const float* __restrict__ bi_r,
    const float* __restrict__ Wh_r, const float* __restrict__ Ws_r, const float* __restrict__ bs_r,
    const float* __restrict__ Wi_z, const float* __restrict__ bi_z,
    const float* __restrict__ Wh_z, const float* __restrict__ Ws_z, const float* __restrict__ bs_z,
    const float* __restrict__ Wi_h, const float* __restrict__ bi_h,
    const float* __restrict__ Wh_h, const float* __restrict__ Wt_h, const float* __restrict__ bt_h)
{
    int tid = threadIdx.x;
    for (int i = tid; i < 672; i += blockDim.x) g_fw[i] = 0.0f;
    __syncthreads();
    for (int idx = tid; idx < 630; idx += blockDim.x) {
        if (idx < 300) {
            int mat = idx / 100, rem = idx % 100, k = rem / 10, j = rem % 10;
            const float* Wi = (mat == 0) ? Wi_r : ((mat == 1) ? Wi_z : Wi_h);
            const float* Ws = (mat == 0) ? Ws_r : ((mat == 1) ? Ws_z : Wt_h);
            float s = 0.0f;
            for (int m = 0; m < 10; ++m) s += Wi[k*10+m] * Ws[m*10+j];
            g_fw[k*32 + mat*10 + j] = s;
        } else if (idx < 500) {
            int m2 = idx - 300; int mat = m2 / 100, rem = m2 % 100, k = rem/10, j = rem%10;
            const float* Wh = (mat == 0) ? Wh_r : Wh_z;
            const float* Ws = (mat == 0) ? Ws_r : Ws_z;
            float s = 0.0f;
            for (int m = 0; m < 10; ++m) s += Wh[k*10+m] * Ws[m*10+j];
            g_fw[320 + k*20 + mat*10 + j] = s;
        } else if (idx < 600) {
            int m2 = idx - 500; int k = m2/10, j = m2%10;
            float s = 0.0f;
            for (int m = 0; m < 10; ++m) s += Wh_h[k*10+m] * Wt_h[m*10+j];
            g_fw[520 + k*12 + j] = s;
        } else {
            int m2 = idx - 600; int mat = m2/10, j = m2%10;
            const float* bi = (mat==0) ? bi_r : ((mat==1) ? bi_z : bi_h);
            const float* Ws = (mat==0) ? Ws_r : ((mat==1) ? Ws_z : Wt_h);
            const float* bs = (mat==0) ? bs_r : ((mat==1) ? bs_z : bt_h);
            float s = bs[j];
            for (int m = 0; m < 10; ++m) s += bi[m]*Ws[m*10+j];
            g_fw[640 + mat*10 + j] = s;
        }
    }
}

__device__ __forceinline__ u64 pk2(float v) {
    u64 r; asm("mov.b64 %0, {%1, %1};" : "=l"(r) : "f"(v)); return r;
}
__device__ __forceinline__ void ff2(u64 &d, u64 a, u64 b) {
    asm("fma.rn.f32x2 %0, %1, %2, %0;" : "+l"(d) : "l"(a), "l"(b));
}
__device__ __forceinline__ void up2(u64 v, float &lo, float &hi) {
    asm("mov.b64 {%0, %1}, %2;" : "=f"(lo), "=f"(hi) : "l"(v));
}
__device__ __forceinline__ float fast_sigmoid(float x) {
    float e; asm("ex2.approx.f32 %0, %1;" : "=f"(e) : "f"(-1.4426950408889634f * x));
    float r; asm("rcp.approx.f32 %0, %1;" : "=f"(r) : "f"(1.0f + e));
    return r;
}
__device__ __forceinline__ float fast_tanh(float x) {
    float e; asm("ex2.approx.f32 %0, %1;" : "=f"(e) : "f"(-2.8853900817779268f * x));
    float r; asm("rcp.approx.f32 %0, %1;" : "=f"(r) : "f"(1.0f + e));
    return 2.0f * r - 1.0f;
}

__global__ void __launch_bounds__(BTH) augru_kernel(
    const float* __restrict__ X, const float* __restrict__ Aat,
    const float* __restrict__ h0, float* __restrict__ out)
{
    __shared__ __align__(16) float sw[672];
    __shared__ float sx[BTH * ROWSTRIDE];
    __shared__ float sa[BTH * ROWSTRIDE];

    int tid = threadIdx.x;
    for (int i = tid; i < 672; i += BTH) sw[i] = g_fw[i];

    int row0 = blockIdx.x * BTH;          // first row of this block
    const float* xg_base = X   + (size_t)row0 * (TT*EE);
    const float* ag_base = Aat + (size_t)row0 * (TT*EE);

    float h[EE];
    #pragma unroll
    for (int j = 0; j < EE; ++j) h[j] = __ldg(h0 + j);

    float* mx = sx + tid * ROWSTRIDE;
    float* ma = sa + tid * ROWSTRIDE;

    for (int c = 0; c < NCHUNK; ++c) {
        __syncthreads();   // previous chunk's readers are done

        // Cooperative coalesced staging: per row, 50 contiguous floats (= 25 float2)
        // of both X and A for timesteps [c*CH, c*CH+CH).
        const float* xg = xg_base + c * (CH*EE);
        const float* ag = ag_base + c * (CH*EE);
        #pragma unroll
        for (int i = 0; i < 25; ++i) {
            int f = tid + i * BTH;            // 0..1599, float2 units
            int r = f / 25;
            int o = f - r * 25;               // float2 offset within row segment
            size_t gofs = (size_t)r * (TT*EE) + (size_t)o * 2;
            float2 vx = *(const float2*)(xg + gofs);
            float2 va = *(const float2*)(ag + gofs);
            int sofs = r * ROWSTRIDE + o * 2;
            sx[sofs] = vx.x; sx[sofs + 1] = vx.y;
            sa[sofs] = va.x; sa[sofs + 1] = va.y;
        }
        __syncthreads();

        #pragma unroll
        for (int tt = 0; tt < CH; ++tt) {
            float x[EE], a[EE];
            #pragma unroll
            for (int j = 0; j < EE; ++j) {
                x[j] = mx[tt*EE + j];
                a[j] = ma[tt*EE + j];
            }

            // init accumulators from fused biases
            u64 aR[5], aZ[5], aH[5];
            {
                const ulonglong2* c2 = (const ulonglong2*)(sw + 640);
                u64 cc[16];
                #pragma unroll
                for (int i = 0; i < 8; ++i) { ulonglong2 v = c2[i]; cc[2*i] = v.x; cc[2*i+1] = v.y; }
                #pragma unroll
                for (int j = 0; j < 5; ++j) {
                    aR[j] = cc[j]; aZ[j] = cc[5+j]; aH[j] = cc[10+j];
                }
            }

            // phase 1: x and h contributions (all gates)
            #pragma unroll
            for (int k = 0; k < EE; ++k) {
                const ulonglong2* xw2 = (const ulonglong2*)(sw + k*32);
                const ulonglong2* hw2 = (const ulonglong2*)(sw + 320 + k*20);
                u64 wx[16], wh[10];
                #pragma unroll
                for (int i = 0; i < 8; ++i) { ulonglong2 v = xw2[i]; wx[2*i] = v.x; wx[2*i+1] = v.y; }
                #pragma unroll
                for (int i = 0; i < 5; ++i) { ulonglong2 v = hw2[i]; wh[2*i] = v.x; wh[2*i+1] = v.y; }

                u64 px = pk2(x[k]);
                u64 ph = pk2(h[k]);
                #pragma unroll
                for (int j = 0; j < 5; ++j) {
                    ff2(aR[j], px, wx[j]);
                    ff2(aZ[j], px, wx[5+j]);
                    ff2(aH[j], px, wx[10+j]);
                    ff2(aR[j], ph, wh[j]);
                    ff2(aZ[j], ph, wh[5+j]);
                }
            }

            // phase 2: r and z gates
            float rg[EE], zg[EE];
            #pragma unroll
            for (int j = 0; j < 5; ++j) {
                float lo, hi;
                up2(aR[j], lo, hi);
                rg[2*j] = fast_sigmoid(lo); rg[2*j+1] = fast_sigmoid(hi);
                up2(aZ[j], lo, hi);
                zg[2*j] = fast_sigmoid(lo); zg[2*j+1] = fast_sigmoid(hi);
            }

            // phase 2b: (h*z) @ B_h
            #pragma unroll
            for (int k = 0; k < EE; ++k) {
                const u64* gw = (const u64*)(sw + 520 + k*12);
                const ulonglong2* gw2 = (const ulonglong2*)gw;
                u64 wg[5];
                { ulonglong2 v0 = gw2[0], v1 = gw2[1];
                  wg[0] = v0.x; wg[1] = v0.y; wg[2] = v1.x; wg[3] = v1.y; wg[4] = gw[4]; }
                u64 pg = pk2(h[k] * zg[k]);
                #pragma unroll
                for (int j = 0; j < 5; ++j) ff2(aH[j], pg, wg[j]);
            }

            // phase 3: candidate + update
            #pragma unroll
            for (int j = 0; j < 5; ++j) {
                float lo, hi; up2(aH[j], lo, hi);
                float hc0 = fast_tanh(lo), hc1 = fast_tanh(hi);
                int j0 = 2*j, j1 = 2*j + 1;
                float Ra0 = a[j0] * rg[j0];
                float Ra1 = a[j1] * rg[j1];
                h[j0] += Ra0 * (hc0 - h[j0]);
                h[j1] += Ra1 * (hc1 - h[j1]);
            }
        }
    }

    // write h_final: 40B per lane, contiguous across warp -> coalesced
    int row = row0 + tid;
    #pragma unroll
    for (int j = 0; j < 5; ++j) {
        *(float2*)(out + (size_t)row*EE + 2*j) = make_float2(h[2*j], h[2*j+1]);
    }
}

extern "C" void kernel_launch(void* const* d_in, const int* in_sizes, int n_in,
                              void* d_out, int out_size)
{
    const float* Xg = (const float*)d_in[0];
    const float* Ag = (const float*)d_in[1];
    const float* h0 = (const float*)d_in[2];

    fuse_kernel<<<1, 256>>>(
        (const float*)d_in[3],  (const float*)d_in[4],  (const float*)d_in[5],
        (const float*)d_in[6],  (const float*)d_in[7],
        (const float*)d_in[8],  (const float*)d_in[9],  (const float*)d_in[10],
        (const float*)d_in[11], (const float*)d_in[12],
        (const float*)d_in[13], (const float*)d_in[14], (const float*)d_in[15],
        (const float*)d_in[16], (const float*)d_in[17]);

    augru_kernel<<<NB / BTH, BTH>>>(Xg, Ag, h0, (float*)d_out);
}

// round 5
// speedup vs baseline: 2.7953x; 2.2968x over previous
#include <cuda_runtime.h>

#define EE 10
#define TT 50
#define NB 65536
#define BTH 256
#define WARPS_TOTAL ((NB + 2) / 3)              // 21846 (3 rows per warp)
#define NBLK ((WARPS_TOTAL + 7) / 8)            // 2731

// Fused weight buffer layout (floats):
// [0..319]   XW: per-k rows of 32: {A_r[k][0..9], A_z[k][0..9], A_h[k][0..9], pad2}
// [320..519] HW: per-k rows of 20: {B_r[k][0..9], B_z[k][0..9]}
// [520..639] GW: per-k rows of 12: {B_h[k][0..9], pad2}
// [640..671] C:  {c_r[0..9], c_z[0..9], c_h[0..9], pad2}
__device__ float g_fw[672];

__global__ void fuse_kernel(
    const float* __restrict__ Wi_r, const float* __restrict__ bi_r,
    const float* __restrict__ Wh_r, const float* __restrict__ Ws_r, const float* __restrict__ bs_r,
    const float* __restrict__ Wi_z, const float* __restrict__ bi_z,
    const float* __restrict__ Wh_z, const float* __restrict__ Ws_z, const float* __restrict__ bs_z,
    const float* __restrict__ Wi_h, const float* __restrict__ bi_h,
    const float* __restrict__ Wh_h, const float* __restrict__ Wt_h, const float* __restrict__ bt_h)
{
    int tid = threadIdx.x;
    for (int i = tid; i < 672; i += blockDim.x) g_fw[i] = 0.0f;
    __syncthreads();
    for (int idx = tid; idx < 630; idx += blockDim.x) {
        if (idx < 300) {
            int mat = idx / 100, rem = idx % 100, k = rem / 10, j = rem % 10;
            const float* Wi = (mat == 0) ? Wi_r : ((mat == 1) ? Wi_z : Wi_h);
            const float* Ws = (mat == 0) ? Ws_r : ((mat == 1) ? Ws_z : Wt_h);
            float s = 0.0f;
            for (int m = 0; m < 10; ++m) s += Wi[k*10+m] * Ws[m*10+j];
            g_fw[k*32 + mat*10 + j] = s;
        } else if (idx < 500) {
            int m2 = idx - 300; int mat = m2 / 100, rem = m2 % 100, k = rem/10, j = rem%10;
            const float* Wh = (mat == 0) ? Wh_r : Wh_z;
            const float* Ws = (mat == 0) ? Ws_r : Ws_z;
            float s = 0.0f;
            for (int m = 0; m < 10; ++m) s += Wh[k*10+m] * Ws[m*10+j];
            g_fw[320 + k*20 + mat*10 + j] = s;
        } else if (idx < 600) {
            int m2 = idx - 500; int k = m2/10, j = m2%10;
            float s = 0.0f;
            for (int m = 0; m < 10; ++m) s += Wh_h[k*10+m] * Wt_h[m*10+j];
            g_fw[520 + k*12 + j] = s;
        } else {
            int m2 = idx - 600; int mat = m2/10, j = m2%10;
            const float* bi = (mat==0) ? bi_r : ((mat==1) ? bi_z : bi_h);
            const float* Ws = (mat==0) ? Ws_r : ((mat==1) ? Ws_z : Wt_h);
            const float* bs = (mat==0) ? bs_r : ((mat==1) ? bs_z : bt_h);
            float s = bs[j];
            for (int m = 0; m < 10; ++m) s += bi[m]*Ws[m*10+j];
            g_fw[640 + mat*10 + j] = s;
        }
    }
}

__device__ __forceinline__ float fast_sigmoid(float x) {
    float e; asm("ex2.approx.f32 %0, %1;" : "=f"(e) : "f"(-1.4426950408889634f * x));
    float r; asm("rcp.approx.f32 %0, %1;" : "=f"(r) : "f"(1.0f + e));
    return r;
}
__device__ __forceinline__ float fast_tanh(float x) {
    float e; asm("ex2.approx.f32 %0, %1;" : "=f"(e) : "f"(-2.8853900817779268f * x));
    float r; asm("rcp.approx.f32 %0, %1;" : "=f"(r) : "f"(1.0f + e));
    return 2.0f * r - 1.0f;
}

// Lane j (of a 10-lane group) owns output column j for one row.
// Weights register-resident: zero weight memory traffic in main loop.
__global__ void __launch_bounds__(BTH) augru_kernel(
    const float* __restrict__ X, const float* __restrict__ Aat,
    const float* __restrict__ h0, float* __restrict__ out)
{
    int wid_g = blockIdx.x * (BTH/32) + (threadIdx.x >> 5);
    int lane  = threadIdx.x & 31;
    int sub   = lane / 10;             // 0,1,2 active; 3 = idle pair
    int col   = lane - sub * 10;       // 0..9 (lanes 30,31 -> 0,1)
    int base  = sub * 10;              // shfl base lane of this row group

    long row = (long)wid_g * 3 + sub;
    bool active = (sub < 3) && (row < NB);
    long row_c = (row < NB) ? row : (NB - 1);

    // Register-resident fused weight columns
    float wAr[EE], wAz[EE], wAh[EE], wBr[EE], wBz[EE], wBh[EE];
    #pragma unroll
    for (int k = 0; k < EE; ++k) {
        wAr[k] = g_fw[k*32 + col];
        wAz[k] = g_fw[k*32 + 10 + col];
        wAh[k] = g_fw[k*32 + 20 + col];
        wBr[k] = g_fw[320 + k*20 + col];
        wBz[k] = g_fw[320 + k*20 + 10 + col];
        wBh[k] = g_fw[520 + k*12 + col];
    }
    float cr = g_fw[640 + col];
    float cz = g_fw[650 + col];
    float ch = g_fw[660 + col];

    float h = __ldg(h0 + col);

    const float* xr = X   + row_c * (TT*EE) + col;
    const float* ar = Aat + row_c * (TT*EE) + col;

    float xc = __ldg(xr);     // x[0][col]

    #pragma unroll 1
    for (int t = 0; t < TT; ++t) {
        // issue loads early; consumed late in the step / next step
        float ac = __ldg(ar + t*EE);                       // a[t][col]
        float xn = (t + 1 < TT) ? __ldg(xr + (t+1)*EE) : 0.0f;

        // gather h and x vectors of this row group
        float hv[EE], xv[EE];
        #pragma unroll
        for (int k = 0; k < EE; ++k) hv[k] = __shfl_sync(0xFFFFFFFFu, h,  base + k);
        #pragma unroll
        for (int k = 0; k < EE; ++k) xv[k] = __shfl_sync(0xFFFFFFFFu, xc, base + k);

        // R and Z preactivations (split accumulators shorten dep chains)
        float pr0 = cr, pr1 = 0.0f, pz0 = cz, pz1 = 0.0f;
        #pragma unroll
        for (int k = 0; k < 5; ++k) {
            pr0 = fmaf(xv[k], wAr[k], pr0); pr0 = fmaf(hv[k], wBr[k], pr0);
            pz0 = fmaf(xv[k], wAz[k], pz0); pz0 = fmaf(hv[k], wBz[k], pz0);
        }
        #pragma unroll
        for (int k = 5; k < EE; ++k) {
            pr1 = fmaf(xv[k], wAr[k], pr1); pr1 = fmaf(hv[k], wBr[k], pr1);
            pz1 = fmaf(xv[k], wAz[k], pz1); pz1 = fmaf(hv[k], wBz[k], pz1);
        }
        float r = fast_sigmoid(pr0 + pr1);
        float z = fast_sigmoid(pz0 + pz1);

        // gated hidden: g[j] = h[j] * z[j] (own column), then gather
        float g = h * z;
        float gv[EE];
        #pragma unroll
        for (int k = 0; k < EE; ++k) gv[k] = __shfl_sync(0xFFFFFFFFu, g, base + k);

        // candidate preactivation
        float ph0 = ch, ph1 = 0.0f;
        #pragma unroll
        for (int k = 0; k < 5; ++k) {
            ph0 = fmaf(xv[k], wAh[k], ph0);
            ph1 = fmaf(gv[k], wBh[k], ph1);
        }
        #pragma unroll
        for (int k = 5; k < EE; ++k) {
            ph0 = fmaf(xv[k], wAh[k], ph0);
            ph1 = fmaf(gv[k], wBh[k], ph1);
        }
        float hc = fast_tanh(ph0 + ph1);

        float Ra = ac * r;
        h = fmaf(Ra, hc - h, h);

        xc = xn;
    }

    if (active) out[row * EE + col] = h;
}

extern "C" void kernel_launch(void* const* d_in, const int* in_sizes, int n_in,
                              void* d_out, int out_size)
{
    const float* Xg = (const float*)d_in[0];
    const float* Ag = (const float*)d_in[1];
    const float* h0 = (const float*)d_in[2];

    fuse_kernel<<<1, 256>>>(
        (const float*)d_in[3],  (const float*)d_in[4],  (const float*)d_in[5],
        (const float*)d_in[6],  (const float*)d_in[7],
        (const float*)d_in[8],  (const float*)d_in[9],  (const float*)d_in[10],
        (const float*)d_in[11], (const float*)d_in[12],
        (const float*)d_in[13], (const float*)d_in[14], (const float*)d_in[15],
        (const float*)d_in[16], (const float*)d_in[17]);

    augru_kernel<<<NBLK, BTH>>>(Xg, Ag, h0, (float*)d_out);
}